// round 1
// baseline (speedup 1.0000x reference)
#include <cuda_runtime.h>
#include <math.h>

// ---------------------------------------------------------------------------
// Problem constants
// ---------------------------------------------------------------------------
#define BB 16
#define LL 4096
#define HH 512
#define PP 256
#define MM (BB * LL)          // 65536 rows
#define KK (2 * PP)           // 512 (re|im concatenated)
#define CH 128                // scan chunk length
#define NCHUNK (LL / CH)      // 32
#define LN_EPS 1e-6f

// ---------------------------------------------------------------------------
// Scratch (static __device__ — no allocation allowed)
// ---------------------------------------------------------------------------
__device__ float g_A1[(size_t)MM * KK];   // Bu then xs, layout [m][0..255]=re, [256..511]=im  (134 MB)
__device__ float g_ys[(size_t)MM * HH];   // ys scratch (134 MB)
__device__ float g_W1[KK * HH];           // [h][n] n<256: Re(Bbar[n][h]), n>=256: Im(Bbar[n][h])
__device__ float g_W2[KK * HH];           // [k'][h] k'=p: 2*C_re[h][p]; k'=256+p: -2*C_im[h][p]
__device__ float g_lbar[2 * PP];          // Lambda_bar re | im
__device__ float g_aC[2 * PP];            // Lambda_bar^CH re | im
__device__ float g_coef[2 * PP];          // (Lambda_bar-1)/Lambda re | im
__device__ float g_carry[BB * NCHUNK * 2 * PP];
__device__ float g_prefix[BB * NCHUNK * 2 * PP];

// ---------------------------------------------------------------------------
// Setup: per-p scalars
// ---------------------------------------------------------------------------
__global__ void k_setup_small(const float* __restrict__ log_lambda_re,
                              const float* __restrict__ lambda_im,
                              const float* __restrict__ log_step) {
    int p = threadIdx.x;
    if (p >= PP) return;
    float lam_re = -expf(log_lambda_re[p]);
    float lam_im = lambda_im[p];
    float st = expf(log_step[p]);
    // Lambda_bar = exp(Lambda*step)
    float ar = lam_re * st, ai = lam_im * st;
    float e = expf(ar);
    float lbr = e * cosf(ai);
    float lbi = e * sinf(ai);
    g_lbar[p] = lbr; g_lbar[PP + p] = lbi;
    // coef = (Lambda_bar - 1) / Lambda
    float nr = lbr - 1.0f, ni = lbi;
    float d2 = lam_re * lam_re + lam_im * lam_im;
    g_coef[p]      = (nr * lam_re + ni * lam_im) / d2;
    g_coef[PP + p] = (ni * lam_re - nr * lam_im) / d2;
    // Lambda_bar^CH via 7 squarings (CH = 128 = 2^7)
    float sr = lbr, si = lbi;
    #pragma unroll
    for (int i = 0; i < 7; i++) {
        float r2 = sr * sr - si * si;
        float i2 = 2.0f * sr * si;
        sr = r2; si = i2;
    }
    g_aC[p] = sr; g_aC[PP + p] = si;
}

// ---------------------------------------------------------------------------
// Setup: build folded weight matrices
// ---------------------------------------------------------------------------
__global__ void k_setup_W(const float* __restrict__ B_re, const float* __restrict__ B_im,
                          const float* __restrict__ C_re, const float* __restrict__ C_im) {
    int idx = blockIdx.x * blockDim.x + threadIdx.x;   // over P*H
    if (idx >= PP * HH) return;
    int p = idx / HH;
    int h = idx % HH;
    float cr = g_coef[p], ci = g_coef[PP + p];
    float br = B_re[p * HH + h], bi = B_im[p * HH + h];
    // Bbar[p][h] = coef[p] * (br + i bi)
    g_W1[h * KK + p]      = cr * br - ci * bi;
    g_W1[h * KK + PP + p] = cr * bi + ci * br;
    // W2
    g_W2[p * HH + h]        =  2.0f * C_re[h * PP + p];
    g_W2[(PP + p) * HH + h] = -2.0f * C_im[h * PP + p];
}

// ---------------------------------------------------------------------------
// fp32 SGEMM: C[M,N] = A[M,K] @ B[K,N], all row-major. M%128==0, N%128==0, K%16==0
// ---------------------------------------------------------------------------
#define BM 128
#define BN 128
#define BKT 16
__global__ __launch_bounds__(256) void k_sgemm(const float* __restrict__ A,
                                               const float* __restrict__ Bm,
                                               float* __restrict__ C,
                                               int M, int N, int K) {
    __shared__ float As[BKT][BM];
    __shared__ float Bs[BKT][BN];
    int bx = blockIdx.x;   // N tiles
    int by = blockIdx.y;   // M tiles
    int tid = threadIdx.x;
    int tr = tid >> 4;     // 0..15
    int tc = tid & 15;     // 0..15

    int arow = tid >> 2;          // 0..63
    int acol = (tid & 3) << 2;    // 0,4,8,12
    int brow = tid >> 5;          // 0..7
    int bcol = (tid & 31) << 2;   // 0..124

    float acc[8][8];
    #pragma unroll
    for (int i = 0; i < 8; i++)
        #pragma unroll
        for (int j = 0; j < 8; j++) acc[i][j] = 0.0f;

    for (int kt = 0; kt < K; kt += BKT) {
        // load A tile (BM x BKT), transposed into As[k][m]
        #pragma unroll
        for (int r = 0; r < BM; r += 64) {
            float4 v = *reinterpret_cast<const float4*>(
                &A[(size_t)(by * BM + arow + r) * K + kt + acol]);
            As[acol + 0][arow + r] = v.x;
            As[acol + 1][arow + r] = v.y;
            As[acol + 2][arow + r] = v.z;
            As[acol + 3][arow + r] = v.w;
        }
        // load B tile (BKT x BN)
        #pragma unroll
        for (int r = 0; r < BKT; r += 8) {
            float4 v = *reinterpret_cast<const float4*>(
                &Bm[(size_t)(kt + brow + r) * N + bx * BN + bcol]);
            *reinterpret_cast<float4*>(&Bs[brow + r][bcol]) = v;
        }
        __syncthreads();
        #pragma unroll
        for (int k = 0; k < BKT; k++) {
            float ar[8], br[8];
            #pragma unroll
            for (int i = 0; i < 8; i++) ar[i] = As[k][tr * 8 + i];
            #pragma unroll
            for (int j = 0; j < 8; j++) br[j] = Bs[k][tc * 8 + j];
            #pragma unroll
            for (int i = 0; i < 8; i++)
                #pragma unroll
                for (int j = 0; j < 8; j++) acc[i][j] += ar[i] * br[j];
        }
        __syncthreads();
    }
    // store
    #pragma unroll
    for (int i = 0; i < 8; i++) {
        size_t row = (size_t)(by * BM + tr * 8 + i) * N + bx * BN + tc * 8;
        float4 v0 = make_float4(acc[i][0], acc[i][1], acc[i][2], acc[i][3]);
        float4 v1 = make_float4(acc[i][4], acc[i][5], acc[i][6], acc[i][7]);
        *reinterpret_cast<float4*>(&C[row]) = v0;
        *reinterpret_cast<float4*>(&C[row + 4]) = v1;
    }
}

// ---------------------------------------------------------------------------
// Scan phase 1: per-chunk carry (read-only over Bu)
// ---------------------------------------------------------------------------
__global__ __launch_bounds__(256) void k_scan_carry() {
    int blk = blockIdx.x;          // b * NCHUNK + j
    int b = blk / NCHUNK;
    int j = blk % NCHUNK;
    int p = threadIdx.x;           // 0..255
    float ar = g_lbar[p], ai = g_lbar[PP + p];
    float sr = 0.0f, si = 0.0f;
    size_t base = ((size_t)b * LL + (size_t)j * CH) * KK + p;
    #pragma unroll 4
    for (int t = 0; t < CH; t++) {
        float br = g_A1[base + (size_t)t * KK];
        float bi = g_A1[base + (size_t)t * KK + PP];
        float nr = fmaf(ar, sr, fmaf(-ai, si, br));
        float ni = fmaf(ar, si, fmaf(ai, sr, bi));
        sr = nr; si = ni;
    }
    g_carry[(size_t)blk * KK + p]      = sr;
    g_carry[(size_t)blk * KK + PP + p] = si;
}

// ---------------------------------------------------------------------------
// Scan phase 2: prefix over chunk carries (tiny)
// ---------------------------------------------------------------------------
__global__ void k_scan_prefix() {
    int b = blockIdx.x;            // 0..15
    int p = threadIdx.x;           // 0..255
    float ar = g_aC[p], ai = g_aC[PP + p];
    float sr = 0.0f, si = 0.0f;
    for (int j = 0; j < NCHUNK; j++) {
        size_t o = (size_t)(b * NCHUNK + j) * KK + p;
        g_prefix[o]      = sr;
        g_prefix[o + PP] = si;
        float cr = g_carry[o], ci = g_carry[o + PP];
        float nr = fmaf(ar, sr, fmaf(-ai, si, cr));
        float ni = fmaf(ar, si, fmaf(ai, sr, ci));
        sr = nr; si = ni;
    }
}

// ---------------------------------------------------------------------------
// Scan phase 3: recompute recurrence seeded with prefix, write xs in place
// ---------------------------------------------------------------------------
__global__ __launch_bounds__(256) void k_scan_apply() {
    int blk = blockIdx.x;
    int b = blk / NCHUNK;
    int j = blk % NCHUNK;
    int p = threadIdx.x;
    float ar = g_lbar[p], ai = g_lbar[PP + p];
    size_t po = (size_t)blk * KK + p;
    float sr = g_prefix[po], si = g_prefix[po + PP];
    size_t base = ((size_t)b * LL + (size_t)j * CH) * KK + p;
    #pragma unroll 4
    for (int t = 0; t < CH; t++) {
        float br = g_A1[base + (size_t)t * KK];
        float bi = g_A1[base + (size_t)t * KK + PP];
        float nr = fmaf(ar, sr, fmaf(-ai, si, br));
        float ni = fmaf(ar, si, fmaf(ai, sr, bi));
        sr = nr; si = ni;
        g_A1[base + (size_t)t * KK]      = sr;
        g_A1[base + (size_t)t * KK + PP] = si;
    }
}

// ---------------------------------------------------------------------------
// Epilogue: y = gelu_tanh(ys + x*D); z = x + y; LayerNorm over H
// ---------------------------------------------------------------------------
__global__ __launch_bounds__(256) void k_epilogue(const float* __restrict__ x,
                                                  const float* __restrict__ D,
                                                  const float* __restrict__ ln_scale,
                                                  const float* __restrict__ ln_bias,
                                                  float* __restrict__ out) {
    int row = blockIdx.x;          // 0..MM-1
    int tid = threadIdx.x;         // 256, 2 elems each
    const float* ysr = g_ys + (size_t)row * HH;
    const float* xr  = x    + (size_t)row * HH;
    float zv[2];
    float sum = 0.0f, sum2 = 0.0f;
    #pragma unroll
    for (int e = 0; e < 2; e++) {
        int h = tid + e * 256;
        float xv = xr[h];
        float y = ysr[h] + xv * D[h];
        // jax.nn.gelu approximate=True (tanh)
        float y3 = y * y * y;
        float u = 0.7978845608028654f * (y + 0.044715f * y3);
        float g = 0.5f * y * (1.0f + tanhf(u));
        float z = xv + g;
        zv[e] = z;
        sum += z; sum2 += z * z;
    }
    // block reduction (8 warps)
    __shared__ float s1[8], s2[8], stats[2];
    #pragma unroll
    for (int off = 16; off > 0; off >>= 1) {
        sum  += __shfl_down_sync(0xFFFFFFFFu, sum, off);
        sum2 += __shfl_down_sync(0xFFFFFFFFu, sum2, off);
    }
    int lane = tid & 31, wid = tid >> 5;
    if (lane == 0) { s1[wid] = sum; s2[wid] = sum2; }
    __syncthreads();
    if (tid == 0) {
        float a = 0.0f, b = 0.0f;
        #pragma unroll
        for (int i = 0; i < 8; i++) { a += s1[i]; b += s2[i]; }
        float mean = a * (1.0f / HH);
        float var = b * (1.0f / HH) - mean * mean;
        stats[0] = mean;
        stats[1] = rsqrtf(var + LN_EPS);
    }
    __syncthreads();
    float mean = stats[0], rstd = stats[1];
    float* outr = out + (size_t)row * HH;
    #pragma unroll
    for (int e = 0; e < 2; e++) {
        int h = tid + e * 256;
        outr[h] = (zv[e] - mean) * rstd * ln_scale[h] + ln_bias[h];
    }
}

// ---------------------------------------------------------------------------
// Launch
// ---------------------------------------------------------------------------
extern "C" void kernel_launch(void* const* d_in, const int* in_sizes, int n_in,
                              void* d_out, int out_size) {
    const float* x             = (const float*)d_in[0];
    const float* log_lambda_re = (const float*)d_in[1];
    const float* lambda_im     = (const float*)d_in[2];
    const float* B_re          = (const float*)d_in[3];
    const float* B_im          = (const float*)d_in[4];
    const float* C_re          = (const float*)d_in[5];
    const float* C_im          = (const float*)d_in[6];
    const float* D             = (const float*)d_in[7];
    const float* log_step      = (const float*)d_in[8];
    const float* ln_scale      = (const float*)d_in[9];
    const float* ln_bias       = (const float*)d_in[10];
    float* out = (float*)d_out;

    // resolve device symbol addresses on the fly inside kernels (they reference
    // the globals directly), so launches only:
    k_setup_small<<<1, 256>>>(log_lambda_re, lambda_im, log_step);
    k_setup_W<<<(PP * HH + 255) / 256, 256>>>(B_re, B_im, C_re, C_im);

    float *gA1, *gys, *gW1, *gW2;
    cudaGetSymbolAddress((void**)&gA1, g_A1);
    cudaGetSymbolAddress((void**)&gys, g_ys);
    cudaGetSymbolAddress((void**)&gW1, g_W1);
    cudaGetSymbolAddress((void**)&gW2, g_W2);

    // GEMM1: Bu = x @ W1   [65536,512]@[512,512]
    dim3 g1(HH / BN, MM / BM);
    k_sgemm<<<g1, 256>>>(x, gW1, gA1, MM, KK, HH);

    // chunked scan
    k_scan_carry<<<BB * NCHUNK, 256>>>();
    k_scan_prefix<<<BB, 256>>>();
    k_scan_apply<<<BB * NCHUNK, 256>>>();

    // GEMM2: ys = xs @ W2  [65536,512]@[512,512]
    k_sgemm<<<g1, 256>>>(gA1, gW2, gys, MM, HH, KK);

    // epilogue
    k_epilogue<<<MM, 256>>>(x, D, ln_scale, ln_bias, out);
}

// round 2
// speedup vs baseline: 2.3556x; 2.3556x over previous
#include <cuda_runtime.h>
#include <cuda_bf16.h>
#include <math.h>
#include <stdint.h>

// ---------------------------------------------------------------------------
// Problem constants
// ---------------------------------------------------------------------------
#define BB 16
#define LL 4096
#define HH 512
#define PP 256
#define MM (BB * LL)          // 65536 rows
#define KK (2 * PP)           // 512 (re|im concatenated)
#define CH 128                // scan chunk length
#define NCHUNK (LL / CH)      // 32
#define LN_EPS 1e-6f

// ---------------------------------------------------------------------------
// Scratch (static __device__ — no allocation allowed)
// ---------------------------------------------------------------------------
__device__ float g_A1[(size_t)MM * KK];   // Bu then xs (fp32, in-place scan)
__device__ float g_ys[(size_t)MM * HH];   // ys scratch
__device__ __nv_bfloat16 g_W1h[KK * HH];  // W1 hi plane  [h][k']  (k'<256 re, >=256 im)
__device__ __nv_bfloat16 g_W1l[KK * HH];  // W1 lo plane
__device__ __nv_bfloat16 g_W2h[KK * HH];  // W2 hi plane  [k'][h]
__device__ __nv_bfloat16 g_W2l[KK * HH];  // W2 lo plane
__device__ float g_lbar[2 * PP];
__device__ float g_aC[2 * PP];
__device__ float g_coef[2 * PP];
__device__ float g_carry[BB * NCHUNK * 2 * PP];
__device__ float g_prefix[BB * NCHUNK * 2 * PP];

// ---------------------------------------------------------------------------
// Setup: per-p scalars
// ---------------------------------------------------------------------------
__global__ void k_setup_small(const float* __restrict__ log_lambda_re,
                              const float* __restrict__ lambda_im,
                              const float* __restrict__ log_step) {
    int p = threadIdx.x;
    if (p >= PP) return;
    float lam_re = -expf(log_lambda_re[p]);
    float lam_im = lambda_im[p];
    float st = expf(log_step[p]);
    float ar = lam_re * st, ai = lam_im * st;
    float e = expf(ar);
    float lbr = e * cosf(ai);
    float lbi = e * sinf(ai);
    g_lbar[p] = lbr; g_lbar[PP + p] = lbi;
    float nr = lbr - 1.0f, ni = lbi;
    float d2 = lam_re * lam_re + lam_im * lam_im;
    g_coef[p]      = (nr * lam_re + ni * lam_im) / d2;
    g_coef[PP + p] = (ni * lam_re - nr * lam_im) / d2;
    float sr = lbr, si = lbi;
    #pragma unroll
    for (int i = 0; i < 7; i++) {
        float r2 = sr * sr - si * si;
        float i2 = 2.0f * sr * si;
        sr = r2; si = i2;
    }
    g_aC[p] = sr; g_aC[PP + p] = si;
}

// ---------------------------------------------------------------------------
// Setup: build folded weight matrices, pre-split into bf16 hi/lo planes
// ---------------------------------------------------------------------------
__device__ __forceinline__ void bf16_split(float v, __nv_bfloat16& h, __nv_bfloat16& l) {
    h = __float2bfloat16_rn(v);
    l = __float2bfloat16_rn(v - __bfloat162float(h));
}

__global__ void k_setup_W(const float* __restrict__ B_re, const float* __restrict__ B_im,
                          const float* __restrict__ C_re, const float* __restrict__ C_im) {
    int idx = blockIdx.x * blockDim.x + threadIdx.x;
    if (idx >= PP * HH) return;
    int p = idx / HH;
    int h = idx % HH;
    float cr = g_coef[p], ci = g_coef[PP + p];
    float br = B_re[p * HH + h], bi = B_im[p * HH + h];
    float w1r = cr * br - ci * bi;
    float w1i = cr * bi + ci * br;
    bf16_split(w1r, g_W1h[h * KK + p],      g_W1l[h * KK + p]);
    bf16_split(w1i, g_W1h[h * KK + PP + p], g_W1l[h * KK + PP + p]);
    bf16_split( 2.0f * C_re[h * PP + p], g_W2h[p * HH + h],        g_W2l[p * HH + h]);
    bf16_split(-2.0f * C_im[h * PP + p], g_W2h[(PP + p) * HH + h], g_W2l[(PP + p) * HH + h]);
}

// ---------------------------------------------------------------------------
// Tensor-core GEMM with bf16 error-compensated split.
// C[M,N] = A[M,K] @ B[K,N].  A fp32 (split in-kernel), B pre-split bf16 planes.
// Block tile 128x128x32, 8 warps, warp tile 64x32, mma.m16n8k16 bf16.
// ---------------------------------------------------------------------------
#define BM 128
#define BN 128
#define BK 32
#define BKP 40    // padded A smem k-stride (bf16 elems)
#define BNP 136   // padded B smem n-stride (bf16 elems)

__device__ __forceinline__ uint32_t s2u(const void* p) {
    return (uint32_t)__cvta_generic_to_shared(p);
}
__device__ __forceinline__ void ldsm4(uint32_t* r, uint32_t a) {
    asm volatile("ldmatrix.sync.aligned.m8n8.x4.shared.b16 {%0,%1,%2,%3},[%4];\n"
                 : "=r"(r[0]), "=r"(r[1]), "=r"(r[2]), "=r"(r[3]) : "r"(a));
}
__device__ __forceinline__ void ldsm4t(uint32_t* r, uint32_t a) {
    asm volatile("ldmatrix.sync.aligned.m8n8.x4.trans.shared.b16 {%0,%1,%2,%3},[%4];\n"
                 : "=r"(r[0]), "=r"(r[1]), "=r"(r[2]), "=r"(r[3]) : "r"(a));
}
__device__ __forceinline__ void mma16816(float* d, const uint32_t* a, uint32_t b0, uint32_t b1) {
    asm volatile("mma.sync.aligned.m16n8k16.row.col.f32.bf16.bf16.f32 "
                 "{%0,%1,%2,%3},{%4,%5,%6,%7},{%8,%9},{%0,%1,%2,%3};\n"
                 : "+f"(d[0]), "+f"(d[1]), "+f"(d[2]), "+f"(d[3])
                 : "r"(a[0]), "r"(a[1]), "r"(a[2]), "r"(a[3]), "r"(b0), "r"(b1));
}

__global__ __launch_bounds__(256, 2) void k_gemm_split(
    const float* __restrict__ A,
    const __nv_bfloat16* __restrict__ Bh,
    const __nv_bfloat16* __restrict__ Bl,
    float* __restrict__ C,
    int M, int N, int K)
{
    __shared__ __align__(16) __nv_bfloat16 Ash[BM * BKP];
    __shared__ __align__(16) __nv_bfloat16 Asl[BM * BKP];
    __shared__ __align__(16) __nv_bfloat16 Bsh[BK * BNP];
    __shared__ __align__(16) __nv_bfloat16 Bsl[BK * BNP];

    int tid = threadIdx.x;
    int bx = blockIdx.x, by = blockIdx.y;
    int lane = tid & 31, wid = tid >> 5;
    int wm = (wid & 1) * 64;    // warp m offset
    int wn = (wid >> 1) * 32;   // warp n offset

    // gmem load indexing
    int arow = tid >> 3;           // 0..31 (+32 steps x4)
    int acol = (tid & 7) * 4;      // fp32 col (float4)
    int brow = tid >> 4;           // 0..15 (+16)
    int bcol = (tid & 15) * 8;     // bf16 col (8 elems)

    // ldmatrix per-lane element offsets
    int a_r = lane & 15;
    int a_c = (lane >> 4) * 8;
    int b_r = (lane & 7) + ((lane >> 3) & 1) * 8;
    int b_c = (lane >> 4) * 8;

    float acc[4][4][4];
    #pragma unroll
    for (int i = 0; i < 4; i++)
        #pragma unroll
        for (int j = 0; j < 4; j++)
            #pragma unroll
            for (int c = 0; c < 4; c++) acc[i][j][c] = 0.0f;

    for (int kt = 0; kt < K; kt += BK) {
        // --- load + split A tile (128x32 fp32 -> hi/lo bf16) ---
        #pragma unroll
        for (int r = 0; r < 4; r++) {
            int row = arow + r * 32;
            float4 v = *reinterpret_cast<const float4*>(
                &A[(size_t)(by * BM + row) * K + kt + acol]);
            float f[4] = {v.x, v.y, v.z, v.w};
            __nv_bfloat16 h[4], l[4];
            #pragma unroll
            for (int e = 0; e < 4; e++) {
                h[e] = __float2bfloat16_rn(f[e]);
                l[e] = __float2bfloat16_rn(f[e] - __bfloat162float(h[e]));
            }
            *reinterpret_cast<uint2*>(&Ash[row * BKP + acol]) = *reinterpret_cast<uint2*>(h);
            *reinterpret_cast<uint2*>(&Asl[row * BKP + acol]) = *reinterpret_cast<uint2*>(l);
        }
        // --- load B tiles (32x128 bf16, two planes) ---
        #pragma unroll
        for (int r = 0; r < 2; r++) {
            int row = brow + r * 16;
            size_t go = (size_t)(kt + row) * N + bx * BN + bcol;
            *reinterpret_cast<float4*>(&Bsh[row * BNP + bcol]) =
                *reinterpret_cast<const float4*>(&Bh[go]);
            *reinterpret_cast<float4*>(&Bsl[row * BNP + bcol]) =
                *reinterpret_cast<const float4*>(&Bl[go]);
        }
        __syncthreads();

        #pragma unroll
        for (int ks = 0; ks < BK; ks += 16) {
            uint32_t bhf[2][4], blf[2][4];
            #pragma unroll
            for (int j2 = 0; j2 < 2; j2++) {
                ldsm4t(bhf[j2], s2u(&Bsh[(ks + b_r) * BNP + wn + j2 * 16 + b_c]));
                ldsm4t(blf[j2], s2u(&Bsl[(ks + b_r) * BNP + wn + j2 * 16 + b_c]));
            }
            #pragma unroll
            for (int i = 0; i < 4; i++) {
                uint32_t ah[4], al[4];
                ldsm4(ah, s2u(&Ash[(wm + i * 16 + a_r) * BKP + ks + a_c]));
                ldsm4(al, s2u(&Asl[(wm + i * 16 + a_r) * BKP + ks + a_c]));
                #pragma unroll
                for (int j = 0; j < 4; j++) {
                    uint32_t b0h = bhf[j >> 1][(j & 1) * 2], b1h = bhf[j >> 1][(j & 1) * 2 + 1];
                    uint32_t b0l = blf[j >> 1][(j & 1) * 2], b1l = blf[j >> 1][(j & 1) * 2 + 1];
                    mma16816(acc[i][j], ah, b0h, b1h);  // hi*hi
                    mma16816(acc[i][j], ah, b0l, b1l);  // hi*lo
                    mma16816(acc[i][j], al, b0h, b1h);  // lo*hi
                }
            }
        }
        __syncthreads();
    }

    // --- store C (fp32) ---
    #pragma unroll
    for (int i = 0; i < 4; i++) {
        int r0 = by * BM + wm + i * 16 + (lane >> 2);
        int c0 = bx * BN + wn + (lane & 3) * 2;
        #pragma unroll
        for (int j = 0; j < 4; j++) {
            *reinterpret_cast<float2*>(&C[(size_t)r0 * N + c0 + j * 8]) =
                make_float2(acc[i][j][0], acc[i][j][1]);
            *reinterpret_cast<float2*>(&C[(size_t)(r0 + 8) * N + c0 + j * 8]) =
                make_float2(acc[i][j][2], acc[i][j][3]);
        }
    }
}

// ---------------------------------------------------------------------------
// Scan phase 1: per-chunk carry (read-only over Bu)
// ---------------------------------------------------------------------------
__global__ __launch_bounds__(256) void k_scan_carry() {
    int blk = blockIdx.x;
    int b = blk / NCHUNK;
    int j = blk % NCHUNK;
    int p = threadIdx.x;
    float ar = g_lbar[p], ai = g_lbar[PP + p];
    float sr = 0.0f, si = 0.0f;
    size_t base = ((size_t)b * LL + (size_t)j * CH) * KK + p;
    #pragma unroll 4
    for (int t = 0; t < CH; t++) {
        float br = g_A1[base + (size_t)t * KK];
        float bi = g_A1[base + (size_t)t * KK + PP];
        float nr = fmaf(ar, sr, fmaf(-ai, si, br));
        float ni = fmaf(ar, si, fmaf(ai, sr, bi));
        sr = nr; si = ni;
    }
    g_carry[(size_t)blk * KK + p]      = sr;
    g_carry[(size_t)blk * KK + PP + p] = si;
}

// ---------------------------------------------------------------------------
// Scan phase 2: prefix over chunk carries (tiny)
// ---------------------------------------------------------------------------
__global__ void k_scan_prefix() {
    int b = blockIdx.x;
    int p = threadIdx.x;
    float ar = g_aC[p], ai = g_aC[PP + p];
    float sr = 0.0f, si = 0.0f;
    for (int j = 0; j < NCHUNK; j++) {
        size_t o = (size_t)(b * NCHUNK + j) * KK + p;
        g_prefix[o]      = sr;
        g_prefix[o + PP] = si;
        float cr = g_carry[o], ci = g_carry[o + PP];
        float nr = fmaf(ar, sr, fmaf(-ai, si, cr));
        float ni = fmaf(ar, si, fmaf(ai, sr, ci));
        sr = nr; si = ni;
    }
}

// ---------------------------------------------------------------------------
// Scan phase 3: recompute recurrence seeded with prefix, write xs in place
// ---------------------------------------------------------------------------
__global__ __launch_bounds__(256) void k_scan_apply() {
    int blk = blockIdx.x;
    int b = blk / NCHUNK;
    int j = blk % NCHUNK;
    int p = threadIdx.x;
    float ar = g_lbar[p], ai = g_lbar[PP + p];
    size_t po = (size_t)blk * KK + p;
    float sr = g_prefix[po], si = g_prefix[po + PP];
    size_t base = ((size_t)b * LL + (size_t)j * CH) * KK + p;
    #pragma unroll 4
    for (int t = 0; t < CH; t++) {
        float br = g_A1[base + (size_t)t * KK];
        float bi = g_A1[base + (size_t)t * KK + PP];
        float nr = fmaf(ar, sr, fmaf(-ai, si, br));
        float ni = fmaf(ar, si, fmaf(ai, sr, bi));
        sr = nr; si = ni;
        g_A1[base + (size_t)t * KK]      = sr;
        g_A1[base + (size_t)t * KK + PP] = si;
    }
}

// ---------------------------------------------------------------------------
// Epilogue: y = gelu_tanh(ys + x*D); z = x + y; LayerNorm over H
// ---------------------------------------------------------------------------
__global__ __launch_bounds__(256) void k_epilogue(const float* __restrict__ x,
                                                  const float* __restrict__ D,
                                                  const float* __restrict__ ln_scale,
                                                  const float* __restrict__ ln_bias,
                                                  float* __restrict__ out) {
    int row = blockIdx.x;
    int tid = threadIdx.x;
    const float* ysr = g_ys + (size_t)row * HH;
    const float* xr  = x    + (size_t)row * HH;
    float zv[2];
    float sum = 0.0f, sum2 = 0.0f;
    #pragma unroll
    for (int e = 0; e < 2; e++) {
        int h = tid + e * 256;
        float xv = xr[h];
        float y = ysr[h] + xv * D[h];
        float y3 = y * y * y;
        float u = 0.7978845608028654f * (y + 0.044715f * y3);
        float g = 0.5f * y * (1.0f + tanhf(u));
        float z = xv + g;
        zv[e] = z;
        sum += z; sum2 += z * z;
    }
    __shared__ float s1[8], s2[8], stats[2];
    #pragma unroll
    for (int off = 16; off > 0; off >>= 1) {
        sum  += __shfl_down_sync(0xFFFFFFFFu, sum, off);
        sum2 += __shfl_down_sync(0xFFFFFFFFu, sum2, off);
    }
    int lane = tid & 31, wid = tid >> 5;
    if (lane == 0) { s1[wid] = sum; s2[wid] = sum2; }
    __syncthreads();
    if (tid == 0) {
        float a = 0.0f, b = 0.0f;
        #pragma unroll
        for (int i = 0; i < 8; i++) { a += s1[i]; b += s2[i]; }
        float mean = a * (1.0f / HH);
        float var = b * (1.0f / HH) - mean * mean;
        stats[0] = mean;
        stats[1] = rsqrtf(var + LN_EPS);
    }
    __syncthreads();
    float mean = stats[0], rstd = stats[1];
    float* outr = out + (size_t)row * HH;
    #pragma unroll
    for (int e = 0; e < 2; e++) {
        int h = tid + e * 256;
        outr[h] = (zv[e] - mean) * rstd * ln_scale[h] + ln_bias[h];
    }
}

// ---------------------------------------------------------------------------
// Launch
// ---------------------------------------------------------------------------
extern "C" void kernel_launch(void* const* d_in, const int* in_sizes, int n_in,
                              void* d_out, int out_size) {
    const float* x             = (const float*)d_in[0];
    const float* log_lambda_re = (const float*)d_in[1];
    const float* lambda_im     = (const float*)d_in[2];
    const float* B_re          = (const float*)d_in[3];
    const float* B_im          = (const float*)d_in[4];
    const float* C_re          = (const float*)d_in[5];
    const float* C_im          = (const float*)d_in[6];
    const float* D             = (const float*)d_in[7];
    const float* log_step      = (const float*)d_in[8];
    const float* ln_scale      = (const float*)d_in[9];
    const float* ln_bias       = (const float*)d_in[10];
    float* out = (float*)d_out;

    k_setup_small<<<1, 256>>>(log_lambda_re, lambda_im, log_step);
    k_setup_W<<<(PP * HH + 255) / 256, 256>>>(B_re, B_im, C_re, C_im);

    float *gA1, *gys;
    __nv_bfloat16 *gW1h, *gW1l, *gW2h, *gW2l;
    cudaGetSymbolAddress((void**)&gA1, g_A1);
    cudaGetSymbolAddress((void**)&gys, g_ys);
    cudaGetSymbolAddress((void**)&gW1h, g_W1h);
    cudaGetSymbolAddress((void**)&gW1l, g_W1l);
    cudaGetSymbolAddress((void**)&gW2h, g_W2h);
    cudaGetSymbolAddress((void**)&gW2l, g_W2l);

    dim3 grid(HH / BN, MM / BM);

    // GEMM1: Bu = x @ W1   [65536,512]@[512,512]
    k_gemm_split<<<grid, 256>>>(x, gW1h, gW1l, gA1, MM, KK, HH);

    // chunked scan over L
    k_scan_carry<<<BB * NCHUNK, 256>>>();
    k_scan_prefix<<<BB, 256>>>();
    k_scan_apply<<<BB * NCHUNK, 256>>>();

    // GEMM2: ys = xs @ W2  [65536,512]@[512,512]
    k_gemm_split<<<grid, 256>>>(gA1, gW2h, gW2l, gys, MM, HH, KK);

    // epilogue
    k_epilogue<<<MM, 256>>>(x, D, ln_scale, ln_bias, out);
}